// round 2
// baseline (speedup 1.0000x reference)
#include <cuda_runtime.h>

#define OUT_DIM 512
#define NUM_S   4096
#define NUM_A   128
#define ELEMS_PER_O (NUM_S * NUM_A)       // 524288 floats per output row
#define V4_PER_O    (ELEMS_PER_O / 4)     // 131072 float4 per output row
#define SPLIT       4
#define V4_PER_BLK  (V4_PER_O / SPLIT)    // 32768 float4 per CTA
#define S_PER_BLK   (NUM_S / SPLIT)       // 1024 s-values per CTA
#define THREADS     256

__global__ void lsh_zero_kernel(float* __restrict__ out) {
    int i = blockIdx.x * blockDim.x + threadIdx.x;
    if (i < OUT_DIM) out[i] = 0.0f;
}

__global__ __launch_bounds__(THREADS)
void lsh_reduce_kernel(const float* __restrict__ x,
                       const float* __restrict__ w,
                       float* __restrict__ out) {
    const int o     = blockIdx.x;   // output index [0, 512)
    const int split = blockIdx.y;   // K-split [0, SPLIT)

    // Stage this CTA's x slice (1024 floats = 4 KB) in shared memory.
    __shared__ float sx[S_PER_BLK];
    {
        const float* xb = x + split * S_PER_BLK;
        #pragma unroll
        for (int i = threadIdx.x; i < S_PER_BLK; i += THREADS)
            sx[i] = xb[i];
    }
    __syncthreads();

    const float4* __restrict__ w4 =
        reinterpret_cast<const float4*>(w)
        + (size_t)o * V4_PER_O
        + (size_t)split * V4_PER_BLK;

    float acc = 0.0f;
    #pragma unroll 8
    for (int i = threadIdx.x; i < V4_PER_BLK; i += THREADS) {
        float4 v = __ldcs(&w4[i]);            // streaming (evict-first) load
        // 32 float4 per s-row -> local s = i >> 5 (warp-uniform -> LDS broadcast)
        acc += sx[i >> 5] * ((v.x + v.y) + (v.z + v.w));
    }

    // warp reduce
    #pragma unroll
    for (int off = 16; off > 0; off >>= 1)
        acc += __shfl_down_sync(0xffffffffu, acc, off);

    __shared__ float sm[THREADS / 32];
    if ((threadIdx.x & 31) == 0) sm[threadIdx.x >> 5] = acc;
    __syncthreads();

    if (threadIdx.x < (THREADS / 32)) {
        float v = sm[threadIdx.x];
        #pragma unroll
        for (int off = (THREADS / 64); off > 0; off >>= 1)
            v += __shfl_down_sync(0xffu, v, off);
        if (threadIdx.x == 0) atomicAdd(&out[o], v);
    }
}

extern "C" void kernel_launch(void* const* d_in, const int* in_sizes, int n_in,
                              void* d_out, int out_size) {
    const float* x = (const float*)d_in[0];  // [1, 4096]
    const float* w = (const float*)d_in[1];  // [512, 4096, 128]
    float* out = (float*)d_out;              // [512]

    lsh_zero_kernel<<<(OUT_DIM + 255) / 256, 256>>>(out);

    dim3 grid(OUT_DIM, SPLIT);
    lsh_reduce_kernel<<<grid, THREADS>>>(x, w, out);
}

// round 3
// speedup vs baseline: 1.0855x; 1.0855x over previous
#include <cuda_runtime.h>

#define OUT_DIM 512
#define NUM_S   4096
#define NUM_A   128
#define ELEMS_PER_O (NUM_S * NUM_A)       // 524288 floats per output row
#define V4_PER_O    (ELEMS_PER_O / 4)     // 131072 float4 per output row
#define SPLIT       4
#define V4_PER_BLK  (V4_PER_O / SPLIT)    // 32768 float4 per CTA
#define THREADS     256

__global__ void lsh_zero_kernel(float* __restrict__ out) {
    int i = blockIdx.x * blockDim.x + threadIdx.x;
    if (i < OUT_DIM) out[i] = 0.0f;
}

__global__ __launch_bounds__(THREADS)
void lsh_reduce_kernel(const float* __restrict__ x,
                       const float* __restrict__ w,
                       float* __restrict__ out) {
    const int o     = blockIdx.x;   // output index [0, 512)
    const int split = blockIdx.y;   // K-split [0, SPLIT)

    const float4* __restrict__ w4 =
        reinterpret_cast<const float4*>(w)
        + (size_t)o * V4_PER_O
        + (size_t)split * V4_PER_BLK;

    const int v4_base = split * V4_PER_BLK;  // global float4 offset within this o

    // Two independent accumulator chains; 2-way interleaved stride loop.
    // V4_PER_BLK / (2*THREADS) = 64 iterations, exact.
    float acc0 = 0.0f, acc1 = 0.0f;
    #pragma unroll 2
    for (int i = threadIdx.x; i < V4_PER_BLK; i += 2 * THREADS) {
        const int j = i + THREADS;
        float4 v0 = w4[i];
        float4 v1 = w4[j];
        float x0 = __ldg(&x[(v4_base + i) >> 5]);  // 32 float4 per s-row
        float x1 = __ldg(&x[(v4_base + j) >> 5]);
        acc0 += x0 * ((v0.x + v0.y) + (v0.z + v0.w));
        acc1 += x1 * ((v1.x + v1.y) + (v1.z + v1.w));
    }
    float acc = acc0 + acc1;

    // warp reduce
    #pragma unroll
    for (int off = 16; off > 0; off >>= 1)
        acc += __shfl_down_sync(0xffffffffu, acc, off);

    __shared__ float sm[THREADS / 32];
    if ((threadIdx.x & 31) == 0) sm[threadIdx.x >> 5] = acc;
    __syncthreads();

    if (threadIdx.x < (THREADS / 32)) {
        float v = sm[threadIdx.x];
        #pragma unroll
        for (int off = (THREADS / 64); off > 0; off >>= 1)
            v += __shfl_down_sync(0xffu, v, off);
        if (threadIdx.x == 0) atomicAdd(&out[o], v);
    }
}

extern "C" void kernel_launch(void* const* d_in, const int* in_sizes, int n_in,
                              void* d_out, int out_size) {
    const float* x = (const float*)d_in[0];  // [1, 4096]
    const float* w = (const float*)d_in[1];  // [512, 4096, 128]
    float* out = (float*)d_out;              // [512]

    lsh_zero_kernel<<<(OUT_DIM + 255) / 256, 256>>>(out);

    dim3 grid(OUT_DIM, SPLIT);
    lsh_reduce_kernel<<<grid, THREADS>>>(x, w, out);
}